// round 6
// baseline (speedup 1.0000x reference)
#include <cuda_runtime.h>

#define HIST_SHIFT 18
#define HIST_N     16384
#define HISTW_N    8192
#define SUB_SHIFT  10
#define SUB_N      1280          // max window = 5 coarse bins = (5<<18)>>10
#define MARGIN     2
#define SAMPLE_DIV 64            // sample first 1/64 of float4 chunks (contiguous)

__device__ unsigned int       g_hist[HIST_N];   // zero at load; select re-zeroes
__device__ unsigned int       g_sub[SUB_N];     // zero at load; finalize re-zeroes
__device__ double             g_sum;            // finalize re-zeroes
__device__ unsigned long long g_cnt;            // finalize re-zeroes
__device__ unsigned int       g_ctrl[4];        // [0]=base_bits [1]=hi_bits [2]=nsub
__device__ unsigned int       g_doneA;          // last-block counters (self-reset)
__device__ unsigned int       g_doneB;

__device__ __forceinline__ float bce_loss(float x, float t) {
    float e  = exp2f(fabsf(x) * -1.44269504f);
    float lg = __log2f(1.0f + e);
    float r  = __fmaf_rn(-x, t, fmaxf(x, 0.0f));
    return fmaxf(__fmaf_rn(0.69314718f, lg, r), 0.0f);
}

// ============ Kernel A: sampled histogram + (last block) select ============
__global__ void __launch_bounds__(512) k_sample_select(const float4* __restrict__ p,
                                                       const float4* __restrict__ t,
                                                       int nchunks,
                                                       unsigned long long ks) {
    __shared__ unsigned sh[HISTW_N];          // 2 x u16 counters per word
    for (int j = threadIdx.x; j < HISTW_N; j += 512) sh[j] = 0u;
    __syncthreads();

    int stride = gridDim.x * blockDim.x;
    for (int s = blockIdx.x * blockDim.x + threadIdx.x; s < nchunks; s += stride) {
        float4 xp = p[s];
        float4 xt = t[s];
        unsigned b;
        b = __float_as_uint(bce_loss(xp.x, xt.x)) >> HIST_SHIFT;
        atomicAdd(&sh[b >> 1], (b & 1u) ? 65536u : 1u);
        b = __float_as_uint(bce_loss(xp.y, xt.y)) >> HIST_SHIFT;
        atomicAdd(&sh[b >> 1], (b & 1u) ? 65536u : 1u);
        b = __float_as_uint(bce_loss(xp.z, xt.z)) >> HIST_SHIFT;
        atomicAdd(&sh[b >> 1], (b & 1u) ? 65536u : 1u);
        b = __float_as_uint(bce_loss(xp.w, xt.w)) >> HIST_SHIFT;
        atomicAdd(&sh[b >> 1], (b & 1u) ? 65536u : 1u);
    }
    __syncthreads();
    for (int j = threadIdx.x; j < HISTW_N; j += 512) {
        unsigned c = sh[j];
        if (c & 0xFFFFu) atomicAdd(&g_hist[2 * j],     c & 0xFFFFu);
        if (c >> 16)     atomicAdd(&g_hist[2 * j + 1], c >> 16);
    }

    // ---- last-block-done handoff ----
    __shared__ int isLast;
    __threadfence();
    if (threadIdx.x == 0) {
        unsigned prev = atomicAdd(&g_doneA, 1u);
        isLast = (prev == gridDim.x - 1);
    }
    __syncthreads();
    if (!isLast) return;
    __threadfence();

    // ---- select (512 threads, 32 bins each) ----
    __shared__ unsigned long long suf[512];
    int tid = threadIdx.x;
    unsigned v[32];
    unsigned long long s = 0;
    int cbase = tid * 32;
    #pragma unroll
    for (int j = 0; j < 32; j++) { v[j] = g_hist[cbase + j]; s += v[j]; }
    #pragma unroll
    for (int j = 0; j < 32; j++) g_hist[cbase + j] = 0u;   // self-clean
    suf[tid] = s;
    __syncthreads();
    for (int off = 1; off < 512; off <<= 1) {
        unsigned long long add = (tid + off < 512) ? suf[tid + off] : 0ull;
        __syncthreads();
        suf[tid] += add;
        __syncthreads();
    }
    unsigned long long nxt = (tid < 511) ? suf[tid + 1] : 0ull;
    if (suf[tid] >= ks && nxt < ks) {
        unsigned long long cum = nxt;
        int bstar = cbase;
        #pragma unroll
        for (int j = 31; j >= 0; j--) {
            cum += v[j];
            if (cum >= ks) { bstar = cbase + j; break; }
        }
        int blo = (bstar >= MARGIN) ? bstar - MARGIN : 0;
        int bhi = (bstar + MARGIN <= HIST_N - 1) ? bstar + MARGIN : HIST_N - 1;
        g_ctrl[0] = (unsigned)blo << HIST_SHIFT;
        g_ctrl[1] = (unsigned)(bhi + 1) << HIST_SHIFT;
        g_ctrl[2] = (((unsigned)(bhi - blo + 1)) << HIST_SHIFT) >> SUB_SHIFT;
    }
    if (tid == 0) g_doneA = 0;   // self-reset
}

// ============ Kernel B: main exact pass + (last block) finalize ============
__device__ __forceinline__ void acc_elem(float x, float t, unsigned base, unsigned hi,
                                         float& fsum, unsigned& lcnt) {
    float v = bce_loss(x, t);
    unsigned b = __float_as_uint(v);
    if (b >= hi)        { fsum += v; lcnt++; }
    else if (b >= base) atomicAdd(&g_sub[(b - base) >> SUB_SHIFT], 1u);
}

__global__ void __launch_bounds__(512) k_main_final(const float4* __restrict__ p,
                                                    const float4* __restrict__ t,
                                                    int n4, long long n,
                                                    long long k,
                                                    float* __restrict__ out) {
    const unsigned base = g_ctrl[0];
    const unsigned hi   = g_ctrl[1];
    float    fsum = 0.0f;
    unsigned lcnt = 0u;

    unsigned stride = gridDim.x * blockDim.x;
    unsigned i = blockIdx.x * blockDim.x + threadIdx.x;
    unsigned n4u = (unsigned)n4;

    for (; i + 3u * stride < n4u; i += 4u * stride) {
        float4 a0 = p[i];
        float4 a1 = p[i + stride];
        float4 a2 = p[i + 2u * stride];
        float4 a3 = p[i + 3u * stride];
        float4 b0 = t[i];
        float4 b1 = t[i + stride];
        float4 b2 = t[i + 2u * stride];
        float4 b3 = t[i + 3u * stride];
        acc_elem(a0.x, b0.x, base, hi, fsum, lcnt);
        acc_elem(a0.y, b0.y, base, hi, fsum, lcnt);
        acc_elem(a0.z, b0.z, base, hi, fsum, lcnt);
        acc_elem(a0.w, b0.w, base, hi, fsum, lcnt);
        acc_elem(a1.x, b1.x, base, hi, fsum, lcnt);
        acc_elem(a1.y, b1.y, base, hi, fsum, lcnt);
        acc_elem(a1.z, b1.z, base, hi, fsum, lcnt);
        acc_elem(a1.w, b1.w, base, hi, fsum, lcnt);
        acc_elem(a2.x, b2.x, base, hi, fsum, lcnt);
        acc_elem(a2.y, b2.y, base, hi, fsum, lcnt);
        acc_elem(a2.z, b2.z, base, hi, fsum, lcnt);
        acc_elem(a2.w, b2.w, base, hi, fsum, lcnt);
        acc_elem(a3.x, b3.x, base, hi, fsum, lcnt);
        acc_elem(a3.y, b3.y, base, hi, fsum, lcnt);
        acc_elem(a3.z, b3.z, base, hi, fsum, lcnt);
        acc_elem(a3.w, b3.w, base, hi, fsum, lcnt);
    }
    for (; i < n4u; i += stride) {
        float4 a0 = p[i];
        float4 b0 = t[i];
        acc_elem(a0.x, b0.x, base, hi, fsum, lcnt);
        acc_elem(a0.y, b0.y, base, hi, fsum, lcnt);
        acc_elem(a0.z, b0.z, base, hi, fsum, lcnt);
        acc_elem(a0.w, b0.w, base, hi, fsum, lcnt);
    }
    if (blockIdx.x == 0 && threadIdx.x == 0) {   // scalar tail (n % 4)
        const float* ps = (const float*)p;
        const float* ts = (const float*)t;
        for (long long j = (long long)n4 * 4; j < n; j++)
            acc_elem(ps[j], ts[j], base, hi, fsum, lcnt);
    }

    // block reduce
    for (int o = 16; o; o >>= 1) {
        fsum += __shfl_down_sync(0xffffffffu, fsum, o);
        lcnt += __shfl_down_sync(0xffffffffu, lcnt, o);
    }
    __shared__ float    ws[16];
    __shared__ unsigned wc[16];
    int wid = threadIdx.x >> 5, lane = threadIdx.x & 31;
    if (lane == 0) { ws[wid] = fsum; wc[wid] = lcnt; }
    __syncthreads();
    if (wid == 0) {
        float    v = (lane < 16) ? ws[lane] : 0.0f;
        unsigned c = (lane < 16) ? wc[lane] : 0u;
        for (int o = 8; o; o >>= 1) {
            v += __shfl_down_sync(0xffffffffu, v, o);
            c += __shfl_down_sync(0xffffffffu, c, o);
        }
        if (lane == 0) {
            atomicAdd(&g_sum, (double)v);
            atomicAdd(&g_cnt, (unsigned long long)c);
        }
    }

    // ---- last-block-done handoff ----
    __shared__ int isLast;
    __threadfence();
    if (threadIdx.x == 0) {
        unsigned prev = atomicAdd(&g_doneB, 1u);
        isLast = (prev == gridDim.x - 1);
    }
    __syncthreads();
    if (!isLast) return;
    __threadfence();

    // ---- finalize (512 threads) ----
    __shared__ unsigned long long sufc[512];
    __shared__ double             sufw[512];
    int tid = threadIdx.x;
    int nsub = (int)g_ctrl[2];                 // <= 1280
    int per  = (nsub + 511) / 512;             // <= 3

    unsigned cs_loc[4];
    unsigned long long c = 0ull;
    double             w = 0.0;
    for (int j = 0; j < per; j++) {
        int s = tid * per + j;
        unsigned cs = (s < nsub) ? g_sub[s] : 0u;
        if (s < nsub) g_sub[s] = 0u;           // self-clean
        cs_loc[j] = cs;
        c += cs;
        if (cs)
            w += (double)cs *
                 (double)__uint_as_float(base + ((unsigned)s << SUB_SHIFT) +
                                         (1u << (SUB_SHIFT - 1)));
    }
    sufc[tid] = c; sufw[tid] = w;
    __syncthreads();
    for (int off = 1; off < 512; off <<= 1) {
        unsigned long long ac = (tid + off < 512) ? sufc[tid + off] : 0ull;
        double             aw = (tid + off < 512) ? sufw[tid + off] : 0.0;
        __syncthreads();
        sufc[tid] += ac; sufw[tid] += aw;
        __syncthreads();
    }

    double    sum_gt = g_sum;
    long long cnt    = (long long)g_cnt;
    __syncthreads();
    if (tid == 0) { g_sum = 0.0; g_cnt = 0ull; g_doneB = 0; }   // self-clean
    long long r = k - cnt;

    if (r <= 0) {
        if (tid == 0) {
            double edge = (double)__uint_as_float(hi);
            out[0] = (float)((sum_gt + (double)r * edge) / (double)k);
        }
        return;
    }
    if ((unsigned long long)r > sufc[0]) {
        if (tid == 0) {
            double res = (sum_gt + sufw[0] +
                          (double)(r - (long long)sufc[0]) *
                          (double)__uint_as_float(base)) / (double)k;
            out[0] = (float)res;
        }
        return;
    }

    unsigned long long nxtc = (tid < 511) ? sufc[tid + 1] : 0ull;
    double             nxtw = (tid < 511) ? sufw[tid + 1] : 0.0;
    if (sufc[tid] >= (unsigned long long)r && nxtc < (unsigned long long)r) {
        unsigned long long cum = nxtc;
        double             acc = nxtw;
        for (int j = per - 1; j >= 0; j--) {
            int s = tid * per + j;
            if (s >= nsub) continue;
            unsigned cs = cs_loc[j];
            double mid = (double)__uint_as_float(base + ((unsigned)s << SUB_SHIFT) +
                                                 (1u << (SUB_SHIFT - 1)));
            if (cum + cs >= (unsigned long long)r) {
                acc += (double)((unsigned long long)r - cum) * mid;
                out[0] = (float)((sum_gt + acc) / (double)k);
                break;
            } else {
                acc += (double)cs * mid;
                cum += cs;
            }
        }
    }
}

// ---------------- host ----------------
extern "C" void kernel_launch(void* const* d_in, const int* in_sizes, int n_in,
                              void* d_out, int out_size) {
    const float* pred = (const float*)d_in[0];
    const float* targ = (const float*)d_in[1];
    long long n  = (long long)in_sizes[0];
    int       n4 = (int)(n / 4);

    int nchunks = n4 / SAMPLE_DIV;
    if (nchunks < 1) nchunks = (n4 > 0) ? n4 : 1;
    unsigned long long sc = (unsigned long long)nchunks * 4ull;
    unsigned long long ks = (unsigned long long)(0.25 * (double)sc);
    if (ks < 1) ks = 1;
    long long kk = (long long)(0.25 * (double)n);
    if (kk < 1) kk = 1;

    k_sample_select<<<148, 512>>>((const float4*)pred, (const float4*)targ,
                                  nchunks, ks);
    k_main_final  <<<592, 512>>>((const float4*)pred, (const float4*)targ,
                                 n4, n, kk, (float*)d_out);
}

// round 10
// speedup vs baseline: 1.0131x; 1.0131x over previous
#include <cuda_runtime.h>

#define HIST_SHIFT 18
#define HIST_N     16384
#define HISTW_N    8192
#define SUB_SHIFT  10
#define SUB_N      1280          // max window = 5 coarse bins = (5<<18)>>10
#define MARGIN     2
#define SAMPLE_DIV 64            // sample first 1/64 of float4 chunks (contiguous)

__device__ unsigned int       g_hist[HIST_N];   // zero at load; select re-zeroes
__device__ unsigned int       g_sub[SUB_N];     // zero at load; finalize re-zeroes
__device__ double             g_sum;            // finalize re-zeroes
__device__ unsigned long long g_cnt;            // finalize re-zeroes
__device__ unsigned int       g_ctrl[4];        // [0]=base_bits [1]=hi_bits [2]=nsub
__device__ unsigned int       g_doneA;          // last-block counters (self-reset)
__device__ unsigned int       g_doneB;

__device__ __forceinline__ float bce_loss(float x, float t) {
    float e  = exp2f(fabsf(x) * -1.44269504f);
    float lg = __log2f(1.0f + e);
    float r  = __fmaf_rn(-x, t, fmaxf(x, 0.0f));
    return fmaxf(__fmaf_rn(0.69314718f, lg, r), 0.0f);
}

// ============ Kernel A: sampled histogram + (last block) select ============
__global__ void __launch_bounds__(512) k_sample_select(const float4* __restrict__ p,
                                                       const float4* __restrict__ t,
                                                       int nchunks,
                                                       unsigned long long ks) {
    __shared__ unsigned sh[HISTW_N];          // 2 x u16 counters per word
    for (int j = threadIdx.x; j < HISTW_N; j += 512) sh[j] = 0u;
    __syncthreads();

    int stride = gridDim.x * blockDim.x;
    for (int s = blockIdx.x * blockDim.x + threadIdx.x; s < nchunks; s += stride) {
        float4 xp = p[s];
        float4 xt = t[s];
        unsigned b;
        b = __float_as_uint(bce_loss(xp.x, xt.x)) >> HIST_SHIFT;
        atomicAdd(&sh[b >> 1], (b & 1u) ? 65536u : 1u);
        b = __float_as_uint(bce_loss(xp.y, xt.y)) >> HIST_SHIFT;
        atomicAdd(&sh[b >> 1], (b & 1u) ? 65536u : 1u);
        b = __float_as_uint(bce_loss(xp.z, xt.z)) >> HIST_SHIFT;
        atomicAdd(&sh[b >> 1], (b & 1u) ? 65536u : 1u);
        b = __float_as_uint(bce_loss(xp.w, xt.w)) >> HIST_SHIFT;
        atomicAdd(&sh[b >> 1], (b & 1u) ? 65536u : 1u);
    }
    __syncthreads();
    for (int j = threadIdx.x; j < HISTW_N; j += 512) {
        unsigned c = sh[j];
        if (c & 0xFFFFu) atomicAdd(&g_hist[2 * j],     c & 0xFFFFu);
        if (c >> 16)     atomicAdd(&g_hist[2 * j + 1], c >> 16);
    }

    // ---- last-block-done handoff ----
    __shared__ int isLast;
    __threadfence();
    if (threadIdx.x == 0) {
        unsigned prev = atomicAdd(&g_doneA, 1u);
        isLast = (prev == gridDim.x - 1);
    }
    __syncthreads();
    if (!isLast) return;
    __threadfence();

    // ---- select (512 threads, 32 bins each) ----
    __shared__ unsigned long long suf[512];
    int tid = threadIdx.x;
    unsigned v[32];
    unsigned long long s = 0;
    int cbase = tid * 32;
    #pragma unroll
    for (int j = 0; j < 32; j++) { v[j] = g_hist[cbase + j]; s += v[j]; }
    #pragma unroll
    for (int j = 0; j < 32; j++) g_hist[cbase + j] = 0u;   // self-clean
    suf[tid] = s;
    __syncthreads();
    for (int off = 1; off < 512; off <<= 1) {
        unsigned long long add = (tid + off < 512) ? suf[tid + off] : 0ull;
        __syncthreads();
        suf[tid] += add;
        __syncthreads();
    }
    unsigned long long nxt = (tid < 511) ? suf[tid + 1] : 0ull;
    if (suf[tid] >= ks && nxt < ks) {
        unsigned long long cum = nxt;
        int bstar = cbase;
        #pragma unroll
        for (int j = 31; j >= 0; j--) {
            cum += v[j];
            if (cum >= ks) { bstar = cbase + j; break; }
        }
        int blo = (bstar >= MARGIN) ? bstar - MARGIN : 0;
        int bhi = (bstar + MARGIN <= HIST_N - 1) ? bstar + MARGIN : HIST_N - 1;
        g_ctrl[0] = (unsigned)blo << HIST_SHIFT;
        g_ctrl[1] = (unsigned)(bhi + 1) << HIST_SHIFT;
        g_ctrl[2] = (((unsigned)(bhi - blo + 1)) << HIST_SHIFT) >> SUB_SHIFT;
    }
    if (tid == 0) g_doneA = 0;   // self-reset
}

// ============ Kernel B: main exact pass (R5 2-way loop) + fused finalize ====
__device__ __forceinline__ void acc_elem(float x, float t, unsigned base, unsigned hi,
                                         float& fsum, unsigned& lcnt) {
    float v = bce_loss(x, t);
    unsigned b = __float_as_uint(v);
    if (b >= hi)        { fsum += v; lcnt++; }
    else if (b >= base) atomicAdd(&g_sub[(b - base) >> SUB_SHIFT], 1u);
}

__global__ void __launch_bounds__(512) k_main_final(const float4* __restrict__ p,
                                                    const float4* __restrict__ t,
                                                    int n4, long long n,
                                                    long long k,
                                                    float* __restrict__ out) {
    const unsigned base = g_ctrl[0];
    const unsigned hi   = g_ctrl[1];
    float    fsum = 0.0f;
    unsigned lcnt = 0u;

    unsigned stride = gridDim.x * blockDim.x;
    unsigned i = blockIdx.x * blockDim.x + threadIdx.x;
    unsigned n4u = (unsigned)n4;

    for (; i + stride < n4u; i += 2u * stride) {
        float4 a0 = p[i];
        float4 b0 = t[i];
        float4 a1 = p[i + stride];
        float4 b1 = t[i + stride];
        acc_elem(a0.x, b0.x, base, hi, fsum, lcnt);
        acc_elem(a0.y, b0.y, base, hi, fsum, lcnt);
        acc_elem(a0.z, b0.z, base, hi, fsum, lcnt);
        acc_elem(a0.w, b0.w, base, hi, fsum, lcnt);
        acc_elem(a1.x, b1.x, base, hi, fsum, lcnt);
        acc_elem(a1.y, b1.y, base, hi, fsum, lcnt);
        acc_elem(a1.z, b1.z, base, hi, fsum, lcnt);
        acc_elem(a1.w, b1.w, base, hi, fsum, lcnt);
    }
    for (; i < n4u; i += stride) {
        float4 a0 = p[i];
        float4 b0 = t[i];
        acc_elem(a0.x, b0.x, base, hi, fsum, lcnt);
        acc_elem(a0.y, b0.y, base, hi, fsum, lcnt);
        acc_elem(a0.z, b0.z, base, hi, fsum, lcnt);
        acc_elem(a0.w, b0.w, base, hi, fsum, lcnt);
    }
    if (blockIdx.x == 0 && threadIdx.x == 0) {   // scalar tail (n % 4)
        const float* ps = (const float*)p;
        const float* ts = (const float*)t;
        for (long long j = (long long)n4 * 4; j < n; j++)
            acc_elem(ps[j], ts[j], base, hi, fsum, lcnt);
    }

    // block reduce
    for (int o = 16; o; o >>= 1) {
        fsum += __shfl_down_sync(0xffffffffu, fsum, o);
        lcnt += __shfl_down_sync(0xffffffffu, lcnt, o);
    }
    __shared__ float    ws[16];
    __shared__ unsigned wc[16];
    int wid = threadIdx.x >> 5, lane = threadIdx.x & 31;
    if (lane == 0) { ws[wid] = fsum; wc[wid] = lcnt; }
    __syncthreads();
    if (wid == 0) {
        float    v = (lane < 16) ? ws[lane] : 0.0f;
        unsigned c = (lane < 16) ? wc[lane] : 0u;
        for (int o = 8; o; o >>= 1) {
            v += __shfl_down_sync(0xffffffffu, v, o);
            c += __shfl_down_sync(0xffffffffu, c, o);
        }
        if (lane == 0) {
            atomicAdd(&g_sum, (double)v);
            atomicAdd(&g_cnt, (unsigned long long)c);
        }
    }

    // ---- last-block-done handoff ----
    __shared__ int isLast;
    __threadfence();
    if (threadIdx.x == 0) {
        unsigned prev = atomicAdd(&g_doneB, 1u);
        isLast = (prev == gridDim.x - 1);
    }
    __syncthreads();
    if (!isLast) return;
    __threadfence();

    // ---- finalize (512 threads) ----
    __shared__ unsigned long long sufc[512];
    __shared__ double             sufw[512];
    int tid = threadIdx.x;
    int nsub = (int)g_ctrl[2];                 // <= 1280
    int per  = (nsub + 511) / 512;             // <= 3

    unsigned cs_loc[4];
    unsigned long long c = 0ull;
    double             w = 0.0;
    for (int j = 0; j < per; j++) {
        int s = tid * per + j;
        unsigned cs = (s < nsub) ? g_sub[s] : 0u;
        if (s < nsub) g_sub[s] = 0u;           // self-clean
        cs_loc[j] = cs;
        c += cs;
        if (cs)
            w += (double)cs *
                 (double)__uint_as_float(base + ((unsigned)s << SUB_SHIFT) +
                                         (1u << (SUB_SHIFT - 1)));
    }
    sufc[tid] = c; sufw[tid] = w;
    __syncthreads();
    for (int off = 1; off < 512; off <<= 1) {
        unsigned long long ac = (tid + off < 512) ? sufc[tid + off] : 0ull;
        double             aw = (tid + off < 512) ? sufw[tid + off] : 0.0;
        __syncthreads();
        sufc[tid] += ac; sufw[tid] += aw;
        __syncthreads();
    }

    double    sum_gt = g_sum;
    long long cnt    = (long long)g_cnt;
    __syncthreads();
    if (tid == 0) { g_sum = 0.0; g_cnt = 0ull; g_doneB = 0; }   // self-clean
    long long r = k - cnt;

    if (r <= 0) {
        if (tid == 0) {
            double edge = (double)__uint_as_float(hi);
            out[0] = (float)((sum_gt + (double)r * edge) / (double)k);
        }
        return;
    }
    if ((unsigned long long)r > sufc[0]) {
        if (tid == 0) {
            double res = (sum_gt + sufw[0] +
                          (double)(r - (long long)sufc[0]) *
                          (double)__uint_as_float(base)) / (double)k;
            out[0] = (float)res;
        }
        return;
    }

    unsigned long long nxtc = (tid < 511) ? sufc[tid + 1] : 0ull;
    double             nxtw = (tid < 511) ? sufw[tid + 1] : 0.0;
    if (sufc[tid] >= (unsigned long long)r && nxtc < (unsigned long long)r) {
        unsigned long long cum = nxtc;
        double             acc = nxtw;
        for (int j = per - 1; j >= 0; j--) {
            int s = tid * per + j;
            if (s >= nsub) continue;
            unsigned cs = cs_loc[j];
            double mid = (double)__uint_as_float(base + ((unsigned)s << SUB_SHIFT) +
                                                 (1u << (SUB_SHIFT - 1)));
            if (cum + cs >= (unsigned long long)r) {
                acc += (double)((unsigned long long)r - cum) * mid;
                out[0] = (float)((sum_gt + acc) / (double)k);
                break;
            } else {
                acc += (double)cs * mid;
                cum += cs;
            }
        }
    }
}

// ---------------- host ----------------
extern "C" void kernel_launch(void* const* d_in, const int* in_sizes, int n_in,
                              void* d_out, int out_size) {
    const float* pred = (const float*)d_in[0];
    const float* targ = (const float*)d_in[1];
    long long n  = (long long)in_sizes[0];
    int       n4 = (int)(n / 4);

    int nchunks = n4 / SAMPLE_DIV;
    if (nchunks < 1) nchunks = (n4 > 0) ? n4 : 1;
    unsigned long long sc = (unsigned long long)nchunks * 4ull;
    unsigned long long ks = (unsigned long long)(0.25 * (double)sc);
    if (ks < 1) ks = 1;
    long long kk = (long long)(0.25 * (double)n);
    if (kk < 1) kk = 1;

    k_sample_select<<<148, 512>>>((const float4*)pred, (const float4*)targ,
                                  nchunks, ks);
    k_main_final  <<<1184, 512>>>((const float4*)pred, (const float4*)targ,
                                  n4, n, kk, (float*)d_out);
}

// round 11
// speedup vs baseline: 1.0331x; 1.0197x over previous
#include <cuda_runtime.h>

#define HIST_SHIFT 18
#define HIST_N     16384
#define HISTW_N    8192
#define SUB_SHIFT  10
#define SUB_N      1280          // max window = 5 coarse bins = (5<<18)>>10
#define MARGIN     2
#define SAMPLE_DIV 64            // sample first 1/64 of float4 chunks (contiguous)

__device__ unsigned int       g_hist[HIST_N];   // zero at load; k_select re-zeroes
__device__ unsigned int       g_sub[SUB_N];     // zero at load; k_final re-zeroes
__device__ double             g_sum;            // k_final re-zeroes
__device__ unsigned long long g_cnt;            // k_final re-zeroes
__device__ unsigned int       g_ctrl[4];        // [0]=base_bits [1]=hi_bits [2]=nsub

__device__ __forceinline__ float bce_loss(float x, float t) {
    float e  = exp2f(fabsf(x) * -1.44269504f);
    float lg = __log2f(1.0f + e);
    float r  = __fmaf_rn(-x, t, fmaxf(x, 0.0f));
    return __fmaf_rn(0.69314718f, lg, r);   // provably >= 0
}

// ---------------- K1: sampled histogram (contiguous prefix, smem-privatized) --
__global__ void __launch_bounds__(512) k_sample(const float4* __restrict__ p,
                                                const float4* __restrict__ t,
                                                int nchunks) {
    __shared__ unsigned sh[HISTW_N];    // 2 x u16 counters per word
    for (int j = threadIdx.x; j < HISTW_N; j += 512) sh[j] = 0u;
    __syncthreads();

    int stride = gridDim.x * blockDim.x;
    for (int s = blockIdx.x * blockDim.x + threadIdx.x; s < nchunks; s += stride) {
        float4 xp = p[s];
        float4 xt = t[s];
        unsigned b;
        b = __float_as_uint(bce_loss(xp.x, xt.x)) >> HIST_SHIFT;
        atomicAdd(&sh[b >> 1], (b & 1u) ? 65536u : 1u);
        b = __float_as_uint(bce_loss(xp.y, xt.y)) >> HIST_SHIFT;
        atomicAdd(&sh[b >> 1], (b & 1u) ? 65536u : 1u);
        b = __float_as_uint(bce_loss(xp.z, xt.z)) >> HIST_SHIFT;
        atomicAdd(&sh[b >> 1], (b & 1u) ? 65536u : 1u);
        b = __float_as_uint(bce_loss(xp.w, xt.w)) >> HIST_SHIFT;
        atomicAdd(&sh[b >> 1], (b & 1u) ? 65536u : 1u);
    }
    __syncthreads();

    for (int j = threadIdx.x; j < HISTW_N; j += 512) {
        unsigned c = sh[j];
        if (c & 0xFFFFu) atomicAdd(&g_hist[2 * j],     c & 0xFFFFu);
        if (c >> 16)     atomicAdd(&g_hist[2 * j + 1], c >> 16);
    }
}

// ---------------- K2: quantile bucket via shfl suffix scans ----------------
__global__ void __launch_bounds__(512) k_select(unsigned long long ks) {
    int tid  = threadIdx.x;
    int lane = tid & 31, wid = tid >> 5;

    unsigned v[32];
    unsigned long long own = 0;
    int cbase = tid * 32;
    #pragma unroll
    for (int j = 0; j < 32; j++) { v[j] = g_hist[cbase + j]; own += v[j]; }
    #pragma unroll
    for (int j = 0; j < 32; j++) g_hist[cbase + j] = 0u;   // self-clean

    // intra-warp inclusive suffix scan of thread sums
    unsigned long long s = own;
    #pragma unroll
    for (int off = 1; off < 32; off <<= 1) {
        unsigned long long u = __shfl_down_sync(0xffffffffu, s, off);
        if (lane + off < 32) s += u;
    }
    __shared__ unsigned long long wtot[16], wtail[17];
    if (lane == 0) wtot[wid] = s;          // lane0 holds warp total
    __syncthreads();
    if (wid == 0) {
        unsigned long long ws = (lane < 16) ? wtot[lane] : 0ull;
        #pragma unroll
        for (int off = 1; off < 16; off <<= 1) {
            unsigned long long u = __shfl_down_sync(0xffffffffu, ws, off);
            if (lane + off < 16) ws += u;
        }
        if (lane < 16) wtail[lane] = ws;   // inclusive suffix over warp totals
        if (lane == 0) wtail[16] = 0ull;
    }
    __syncthreads();

    unsigned long long S = s + wtail[wid + 1];   // suffix sum from this thread
    if (S >= ks && S - own < ks) {
        unsigned long long cum = S - own;
        int bstar = cbase;
        #pragma unroll
        for (int j = 31; j >= 0; j--) {
            cum += v[j];
            if (cum >= ks) { bstar = cbase + j; break; }
        }
        int blo = (bstar >= MARGIN) ? bstar - MARGIN : 0;
        int bhi = (bstar + MARGIN <= HIST_N - 1) ? bstar + MARGIN : HIST_N - 1;
        g_ctrl[0] = (unsigned)blo << HIST_SHIFT;
        g_ctrl[1] = (unsigned)(bhi + 1) << HIST_SHIFT;
        g_ctrl[2] = (((unsigned)(bhi - blo + 1)) << HIST_SHIFT) >> SUB_SHIFT;
    }
}

// ---------------- K3: main exact pass (R5 shape + __ldcs) ----------------
__device__ __forceinline__ void acc_elem(float x, float t, unsigned base, unsigned hi,
                                         float& fsum, unsigned& lcnt) {
    float v = bce_loss(x, t);
    unsigned b = __float_as_uint(v);
    if (b >= hi)        { fsum += v; lcnt++; }
    else if (b >= base) atomicAdd(&g_sub[(b - base) >> SUB_SHIFT], 1u);
}

__global__ void __launch_bounds__(512) k_main(const float4* __restrict__ p,
                                              const float4* __restrict__ t,
                                              int n4, long long n) {
    const unsigned base = g_ctrl[0];
    const unsigned hi   = g_ctrl[1];
    float    fsum = 0.0f;
    unsigned lcnt = 0u;

    unsigned stride = gridDim.x * blockDim.x;
    unsigned i = blockIdx.x * blockDim.x + threadIdx.x;
    unsigned n4u = (unsigned)n4;

    for (; i + stride < n4u; i += 2u * stride) {
        float4 a0 = __ldcs(p + i);
        float4 b0 = __ldcs(t + i);
        float4 a1 = __ldcs(p + i + stride);
        float4 b1 = __ldcs(t + i + stride);
        acc_elem(a0.x, b0.x, base, hi, fsum, lcnt);
        acc_elem(a0.y, b0.y, base, hi, fsum, lcnt);
        acc_elem(a0.z, b0.z, base, hi, fsum, lcnt);
        acc_elem(a0.w, b0.w, base, hi, fsum, lcnt);
        acc_elem(a1.x, b1.x, base, hi, fsum, lcnt);
        acc_elem(a1.y, b1.y, base, hi, fsum, lcnt);
        acc_elem(a1.z, b1.z, base, hi, fsum, lcnt);
        acc_elem(a1.w, b1.w, base, hi, fsum, lcnt);
    }
    for (; i < n4u; i += stride) {
        float4 a0 = __ldcs(p + i);
        float4 b0 = __ldcs(t + i);
        acc_elem(a0.x, b0.x, base, hi, fsum, lcnt);
        acc_elem(a0.y, b0.y, base, hi, fsum, lcnt);
        acc_elem(a0.z, b0.z, base, hi, fsum, lcnt);
        acc_elem(a0.w, b0.w, base, hi, fsum, lcnt);
    }
    if (blockIdx.x == 0 && threadIdx.x == 0) {   // scalar tail (n % 4)
        const float* ps = (const float*)p;
        const float* ts = (const float*)t;
        for (long long j = (long long)n4 * 4; j < n; j++)
            acc_elem(ps[j], ts[j], base, hi, fsum, lcnt);
    }

    for (int o = 16; o; o >>= 1) {
        fsum += __shfl_down_sync(0xffffffffu, fsum, o);
        lcnt += __shfl_down_sync(0xffffffffu, lcnt, o);
    }
    __shared__ float    ws[16];
    __shared__ unsigned wc[16];
    int wid = threadIdx.x >> 5, lane = threadIdx.x & 31;
    if (lane == 0) { ws[wid] = fsum; wc[wid] = lcnt; }
    __syncthreads();
    if (wid == 0) {
        float    v = (lane < 16) ? ws[lane] : 0.0f;
        unsigned c = (lane < 16) ? wc[lane] : 0u;
        for (int o = 8; o; o >>= 1) {
            v += __shfl_down_sync(0xffffffffu, v, o);
            c += __shfl_down_sync(0xffffffffu, c, o);
        }
        if (lane == 0) {
            atomicAdd(&g_sum, (double)v);
            atomicAdd(&g_cnt, (unsigned long long)c);
        }
    }
}

// ---------------- K4: finalize via shfl suffix scans (256 threads) ----------
__global__ void __launch_bounds__(256) k_final(long long k, float* __restrict__ out) {
    int tid  = threadIdx.x;
    int lane = tid & 31, wid = tid >> 5;
    unsigned base = g_ctrl[0];
    int nsub = (int)g_ctrl[2];                 // <= 1280
    int per  = (nsub + 255) / 256;             // <= 5

    double    sum_gt = g_sum;
    long long cnt    = (long long)g_cnt;

    unsigned cs_loc[5];
    unsigned long long ownc = 0ull;
    double             ownw = 0.0;
    #pragma unroll
    for (int j = 0; j < 5; j++) {
        int s = tid * per + j;
        unsigned cs = (j < per && s < nsub) ? g_sub[s] : 0u;
        if (j < per && s < nsub) g_sub[s] = 0u;    // self-clean
        cs_loc[j] = cs;
        ownc += cs;
        if (cs)
            ownw += (double)cs *
                    (double)__uint_as_float(base + ((unsigned)s << SUB_SHIFT) +
                                            (1u << (SUB_SHIFT - 1)));
    }

    // intra-warp inclusive suffix scans
    unsigned long long sc = ownc;
    double             sw = ownw;
    #pragma unroll
    for (int off = 1; off < 32; off <<= 1) {
        unsigned long long uc = __shfl_down_sync(0xffffffffu, sc, off);
        double             uw = __shfl_down_sync(0xffffffffu, sw, off);
        if (lane + off < 32) { sc += uc; sw += uw; }
    }
    __shared__ unsigned long long wtc[8], wtailc[9];
    __shared__ double             wtw[8], wtailw[9];
    if (lane == 0) { wtc[wid] = sc; wtw[wid] = sw; }
    __syncthreads();
    if (wid == 0) {
        unsigned long long c8 = (lane < 8) ? wtc[lane] : 0ull;
        double             w8 = (lane < 8) ? wtw[lane] : 0.0;
        #pragma unroll
        for (int off = 1; off < 8; off <<= 1) {
            unsigned long long uc = __shfl_down_sync(0xffffffffu, c8, off);
            double             uw = __shfl_down_sync(0xffffffffu, w8, off);
            if (lane + off < 8) { c8 += uc; w8 += uw; }
        }
        if (lane < 8) { wtailc[lane] = c8; wtailw[lane] = w8; }
        if (lane == 0) { wtailc[8] = 0ull; wtailw[8] = 0.0; }
    }
    __syncthreads();
    if (tid == 0) { g_sum = 0.0; g_cnt = 0ull; }   // self-clean

    unsigned long long Sc = sc + wtailc[wid + 1];
    double             Sw = sw + wtailw[wid + 1];
    unsigned long long totC = wtailc[0];
    double             totW = wtailw[0];

    long long r = k - cnt;
    if (r <= 0) {
        if (tid == 0) {
            double edge = (double)__uint_as_float(g_ctrl[1]);
            out[0] = (float)((sum_gt + (double)r * edge) / (double)k);
        }
        return;
    }
    if ((unsigned long long)r > totC) {
        if (tid == 0) {
            double res = (sum_gt + totW +
                          (double)(r - (long long)totC) *
                          (double)__uint_as_float(base)) / (double)k;
            out[0] = (float)res;
        }
        return;
    }

    if (Sc >= (unsigned long long)r && Sc - ownc < (unsigned long long)r) {
        unsigned long long cum = Sc - ownc;
        double             acc = Sw - ownw;
        for (int j = per - 1; j >= 0; j--) {
            int s = tid * per + j;
            if (s >= nsub) continue;
            unsigned cs = cs_loc[j];
            double mid = (double)__uint_as_float(base + ((unsigned)s << SUB_SHIFT) +
                                                 (1u << (SUB_SHIFT - 1)));
            if (cum + cs >= (unsigned long long)r) {
                acc += (double)((unsigned long long)r - cum) * mid;
                out[0] = (float)((sum_gt + acc) / (double)k);
                break;
            } else {
                acc += (double)cs * mid;
                cum += cs;
            }
        }
    }
}

// ---------------- host ----------------
extern "C" void kernel_launch(void* const* d_in, const int* in_sizes, int n_in,
                              void* d_out, int out_size) {
    const float* pred = (const float*)d_in[0];
    const float* targ = (const float*)d_in[1];
    long long n  = (long long)in_sizes[0];
    int       n4 = (int)(n / 4);

    int nchunks = n4 / SAMPLE_DIV;
    if (nchunks < 1) nchunks = (n4 > 0) ? n4 : 1;
    unsigned long long sc = (unsigned long long)nchunks * 4ull;
    unsigned long long ks = (unsigned long long)(0.25 * (double)sc);
    if (ks < 1) ks = 1;
    long long kk = (long long)(0.25 * (double)n);
    if (kk < 1) kk = 1;

    k_sample<<<148, 512>>>((const float4*)pred, (const float4*)targ, nchunks);
    k_select<<<1, 512>>>(ks);
    k_main  <<<1184, 512>>>((const float4*)pred, (const float4*)targ, n4, n);
    k_final <<<1, 256>>>(kk, (float*)d_out);
}

// round 12
// speedup vs baseline: 1.8829x; 1.8226x over previous
#include <cuda_runtime.h>

#define HIST_SHIFT 18
#define HIST_N     16384
#define HISTW_N    8192
#define SUB_SHIFT  10
#define SUB_N      1280          // max window = 5 coarse bins = (5<<18)>>10
#define MARGIN     2
#define SAMPLE_DIV 64            // sample first 1/64 of float4 chunks (contiguous)

__device__ unsigned int       g_hist[HIST_N];   // zero at load; select re-zeroes
__device__ unsigned int       g_sub[SUB_N];     // zero at load; finalize re-zeroes
__device__ double             g_sum;            // finalize re-zeroes
__device__ unsigned long long g_cnt;            // finalize re-zeroes
__device__ unsigned int       g_ctrl[4];        // [0]=base_bits [1]=hi_bits [2]=nsub
__device__ unsigned int       g_doneA;          // last-block counters (self-reset)
__device__ unsigned int       g_doneB;

__device__ __forceinline__ float bce_loss(float x, float t) {
    float e  = exp2f(fabsf(x) * -1.44269504f);
    float lg = __log2f(1.0f + e);
    float r  = __fmaf_rn(-x, t, fmaxf(x, 0.0f));
    return __fmaf_rn(0.69314718f, lg, r);   // >= 0 (r,lg >= 0)
}

// ============ Kernel A: sampled histogram + (last block) select ============
__global__ void __launch_bounds__(512) k_sample_select(const float4* __restrict__ p,
                                                       const float4* __restrict__ t,
                                                       int nchunks,
                                                       unsigned long long ks) {
    __shared__ unsigned sh[HISTW_N];          // 2 x u16 counters per word
    for (int j = threadIdx.x; j < HISTW_N; j += 512) sh[j] = 0u;
    __syncthreads();

    int stride = gridDim.x * blockDim.x;
    for (int s = blockIdx.x * blockDim.x + threadIdx.x; s < nchunks; s += stride) {
        float4 xp = p[s];
        float4 xt = t[s];
        unsigned b;
        b = __float_as_uint(bce_loss(xp.x, xt.x)) >> HIST_SHIFT;
        atomicAdd(&sh[b >> 1], (b & 1u) ? 65536u : 1u);
        b = __float_as_uint(bce_loss(xp.y, xt.y)) >> HIST_SHIFT;
        atomicAdd(&sh[b >> 1], (b & 1u) ? 65536u : 1u);
        b = __float_as_uint(bce_loss(xp.z, xt.z)) >> HIST_SHIFT;
        atomicAdd(&sh[b >> 1], (b & 1u) ? 65536u : 1u);
        b = __float_as_uint(bce_loss(xp.w, xt.w)) >> HIST_SHIFT;
        atomicAdd(&sh[b >> 1], (b & 1u) ? 65536u : 1u);
    }
    __syncthreads();
    for (int j = threadIdx.x; j < HISTW_N; j += 512) {
        unsigned c = sh[j];
        if (c & 0xFFFFu) atomicAdd(&g_hist[2 * j],     c & 0xFFFFu);
        if (c >> 16)     atomicAdd(&g_hist[2 * j + 1], c >> 16);
    }

    // ---- last-block-done handoff ----
    __shared__ int isLast;
    __threadfence();
    if (threadIdx.x == 0) {
        unsigned prev = atomicAdd(&g_doneA, 1u);
        isLast = (prev == gridDim.x - 1);
    }
    __syncthreads();
    if (!isLast) return;
    __threadfence();

    // ---- select (512 threads, 32 bins each) ----
    __shared__ unsigned long long suf[512];
    int tid = threadIdx.x;
    unsigned v[32];
    unsigned long long s = 0;
    int cbase = tid * 32;
    #pragma unroll
    for (int j = 0; j < 32; j++) { v[j] = g_hist[cbase + j]; s += v[j]; }
    #pragma unroll
    for (int j = 0; j < 32; j++) g_hist[cbase + j] = 0u;   // self-clean
    suf[tid] = s;
    __syncthreads();
    for (int off = 1; off < 512; off <<= 1) {
        unsigned long long add = (tid + off < 512) ? suf[tid + off] : 0ull;
        __syncthreads();
        suf[tid] += add;
        __syncthreads();
    }
    unsigned long long nxt = (tid < 511) ? suf[tid + 1] : 0ull;
    if (suf[tid] >= ks && nxt < ks) {
        unsigned long long cum = nxt;
        int bstar = cbase;
        #pragma unroll
        for (int j = 31; j >= 0; j--) {
            cum += v[j];
            if (cum >= ks) { bstar = cbase + j; break; }
        }
        int blo = (bstar >= MARGIN) ? bstar - MARGIN : 0;
        int bhi = (bstar + MARGIN <= HIST_N - 1) ? bstar + MARGIN : HIST_N - 1;
        g_ctrl[0] = (unsigned)blo << HIST_SHIFT;
        g_ctrl[1] = (unsigned)(bhi + 1) << HIST_SHIFT;
        g_ctrl[2] = (((unsigned)(bhi - blo + 1)) << HIST_SHIFT) >> SUB_SHIFT;
    }
    if (tid == 0) g_doneA = 0;   // self-reset
}

// ============ Kernel B: pipelined main pass + smem sub-hist + finalize ======
__global__ void __launch_bounds__(512) k_main_final(const float4* __restrict__ p,
                                                    const float4* __restrict__ t,
                                                    int n4, long long n,
                                                    long long k,
                                                    float* __restrict__ out) {
    __shared__ unsigned shsub[SUB_N];
    for (int j = threadIdx.x; j < SUB_N; j += 512) shsub[j] = 0u;
    __syncthreads();

    const unsigned base = g_ctrl[0];
    const unsigned hi   = g_ctrl[1];
    float    fsum = 0.0f;
    unsigned lcnt = 0u;

    const unsigned stride = gridDim.x * blockDim.x;
    unsigned i = blockIdx.x * blockDim.x + threadIdx.x;
    const unsigned n4u = (unsigned)n4;

    if (i < n4u) {
        float4 a = p[i];
        float4 b = t[i];
        for (;;) {
            unsigned j = i + stride;
            if (j < n4u) {
                float4 an = p[j];                 // prefetch next iteration
                float4 bn = t[j];
                {   // process current
                    float v; unsigned bb;
                    v = bce_loss(a.x, b.x); bb = __float_as_uint(v);
                    if (bb >= hi) { fsum += v; lcnt++; }
                    else if (bb >= base) atomicAdd(&shsub[(bb - base) >> SUB_SHIFT], 1u);
                    v = bce_loss(a.y, b.y); bb = __float_as_uint(v);
                    if (bb >= hi) { fsum += v; lcnt++; }
                    else if (bb >= base) atomicAdd(&shsub[(bb - base) >> SUB_SHIFT], 1u);
                    v = bce_loss(a.z, b.z); bb = __float_as_uint(v);
                    if (bb >= hi) { fsum += v; lcnt++; }
                    else if (bb >= base) atomicAdd(&shsub[(bb - base) >> SUB_SHIFT], 1u);
                    v = bce_loss(a.w, b.w); bb = __float_as_uint(v);
                    if (bb >= hi) { fsum += v; lcnt++; }
                    else if (bb >= base) atomicAdd(&shsub[(bb - base) >> SUB_SHIFT], 1u);
                }
                a = an; b = bn; i = j;
            } else {
                float v; unsigned bb;
                v = bce_loss(a.x, b.x); bb = __float_as_uint(v);
                if (bb >= hi) { fsum += v; lcnt++; }
                else if (bb >= base) atomicAdd(&shsub[(bb - base) >> SUB_SHIFT], 1u);
                v = bce_loss(a.y, b.y); bb = __float_as_uint(v);
                if (bb >= hi) { fsum += v; lcnt++; }
                else if (bb >= base) atomicAdd(&shsub[(bb - base) >> SUB_SHIFT], 1u);
                v = bce_loss(a.z, b.z); bb = __float_as_uint(v);
                if (bb >= hi) { fsum += v; lcnt++; }
                else if (bb >= base) atomicAdd(&shsub[(bb - base) >> SUB_SHIFT], 1u);
                v = bce_loss(a.w, b.w); bb = __float_as_uint(v);
                if (bb >= hi) { fsum += v; lcnt++; }
                else if (bb >= base) atomicAdd(&shsub[(bb - base) >> SUB_SHIFT], 1u);
                break;
            }
        }
    }
    if (blockIdx.x == 0 && threadIdx.x == 0) {   // scalar tail (n % 4)
        const float* ps = (const float*)p;
        const float* ts = (const float*)t;
        for (long long j = (long long)n4 * 4; j < n; j++) {
            float v = bce_loss(ps[j], ts[j]);
            unsigned bb = __float_as_uint(v);
            if (bb >= hi) { fsum += v; lcnt++; }
            else if (bb >= base) atomicAdd(&shsub[(bb - base) >> SUB_SHIFT], 1u);
        }
    }

    // block reduce of sum/cnt
    for (int o = 16; o; o >>= 1) {
        fsum += __shfl_down_sync(0xffffffffu, fsum, o);
        lcnt += __shfl_down_sync(0xffffffffu, lcnt, o);
    }
    __shared__ float    ws[16];
    __shared__ unsigned wc[16];
    int wid = threadIdx.x >> 5, lane = threadIdx.x & 31;
    if (lane == 0) { ws[wid] = fsum; wc[wid] = lcnt; }
    __syncthreads();
    if (wid == 0) {
        float    v = (lane < 16) ? ws[lane] : 0.0f;
        unsigned c = (lane < 16) ? wc[lane] : 0u;
        for (int o = 8; o; o >>= 1) {
            v += __shfl_down_sync(0xffffffffu, v, o);
            c += __shfl_down_sync(0xffffffffu, c, o);
        }
        if (lane == 0) {
            atomicAdd(&g_sum, (double)v);
            atomicAdd(&g_cnt, (unsigned long long)c);
        }
    }

    // flush block-private sub-histogram (nonzero bins only)
    __syncthreads();
    for (int j = threadIdx.x; j < SUB_N; j += 512) {
        unsigned c = shsub[j];
        if (c) atomicAdd(&g_sub[j], c);
    }

    // ---- last-block-done handoff ----
    __shared__ int isLast;
    __threadfence();
    if (threadIdx.x == 0) {
        unsigned prev = atomicAdd(&g_doneB, 1u);
        isLast = (prev == gridDim.x - 1);
    }
    __syncthreads();
    if (!isLast) return;
    __threadfence();

    // ---- finalize (512 threads) ----
    __shared__ unsigned long long sufc[512];
    __shared__ double             sufw[512];
    int tid = threadIdx.x;
    int nsub = (int)g_ctrl[2];                 // <= 1280
    int per  = (nsub + 511) / 512;             // <= 3

    unsigned cs_loc[4];
    unsigned long long c = 0ull;
    double             w = 0.0;
    for (int j = 0; j < per; j++) {
        int s = tid * per + j;
        unsigned cs = (s < nsub) ? g_sub[s] : 0u;
        if (s < nsub) g_sub[s] = 0u;           // self-clean
        cs_loc[j] = cs;
        c += cs;
        if (cs)
            w += (double)cs *
                 (double)__uint_as_float(base + ((unsigned)s << SUB_SHIFT) +
                                         (1u << (SUB_SHIFT - 1)));
    }
    sufc[tid] = c; sufw[tid] = w;
    __syncthreads();
    for (int off = 1; off < 512; off <<= 1) {
        unsigned long long ac = (tid + off < 512) ? sufc[tid + off] : 0ull;
        double             aw = (tid + off < 512) ? sufw[tid + off] : 0.0;
        __syncthreads();
        sufc[tid] += ac; sufw[tid] += aw;
        __syncthreads();
    }

    double    sum_gt = g_sum;
    long long cnt    = (long long)g_cnt;
    __syncthreads();
    if (tid == 0) { g_sum = 0.0; g_cnt = 0ull; g_doneB = 0; }   // self-clean
    long long r = k - cnt;

    if (r <= 0) {
        if (tid == 0) {
            double edge = (double)__uint_as_float(hi);
            out[0] = (float)((sum_gt + (double)r * edge) / (double)k);
        }
        return;
    }
    if ((unsigned long long)r > sufc[0]) {
        if (tid == 0) {
            double res = (sum_gt + sufw[0] +
                          (double)(r - (long long)sufc[0]) *
                          (double)__uint_as_float(base)) / (double)k;
            out[0] = (float)res;
        }
        return;
    }

    unsigned long long nxtc = (tid < 511) ? sufc[tid + 1] : 0ull;
    double             nxtw = (tid < 511) ? sufw[tid + 1] : 0.0;
    if (sufc[tid] >= (unsigned long long)r && nxtc < (unsigned long long)r) {
        unsigned long long cum = nxtc;
        double             acc = nxtw;
        for (int j = per - 1; j >= 0; j--) {
            int s = tid * per + j;
            if (s >= nsub) continue;
            unsigned cs = cs_loc[j];
            double mid = (double)__uint_as_float(base + ((unsigned)s << SUB_SHIFT) +
                                                 (1u << (SUB_SHIFT - 1)));
            if (cum + cs >= (unsigned long long)r) {
                acc += (double)((unsigned long long)r - cum) * mid;
                out[0] = (float)((sum_gt + acc) / (double)k);
                break;
            } else {
                acc += (double)cs * mid;
                cum += cs;
            }
        }
    }
}

// ---------------- host ----------------
extern "C" void kernel_launch(void* const* d_in, const int* in_sizes, int n_in,
                              void* d_out, int out_size) {
    const float* pred = (const float*)d_in[0];
    const float* targ = (const float*)d_in[1];
    long long n  = (long long)in_sizes[0];
    int       n4 = (int)(n / 4);

    int nchunks = n4 / SAMPLE_DIV;
    if (nchunks < 1) nchunks = (n4 > 0) ? n4 : 1;
    unsigned long long sc = (unsigned long long)nchunks * 4ull;
    unsigned long long ks = (unsigned long long)(0.25 * (double)sc);
    if (ks < 1) ks = 1;
    long long kk = (long long)(0.25 * (double)n);
    if (kk < 1) kk = 1;

    k_sample_select<<<148, 512>>>((const float4*)pred, (const float4*)targ,
                                  nchunks, ks);
    k_main_final  <<<1184, 512>>>((const float4*)pred, (const float4*)targ,
                                  n4, n, kk, (float*)d_out);
}

// round 13
// speedup vs baseline: 1.9520x; 1.0367x over previous
#include <cuda_runtime.h>

#define HIST_SHIFT 18
#define HIST_N     16384
#define HISTW_N    8192
#define SUB_SHIFT  10
#define SUB_N      1280          // max window = 5 coarse bins = (5<<18)>>10
#define MARGIN     2
#define SAMPLE_DIV 64            // sample first 1/64 of float4 chunks (contiguous)

__device__ unsigned int       g_hist[HIST_N];   // zero at load; select re-zeroes
__device__ unsigned int       g_sub[SUB_N];     // zero at load; finalize re-zeroes
__device__ double             g_sum;            // finalize re-zeroes
__device__ unsigned long long g_cnt;            // finalize re-zeroes
__device__ unsigned int       g_ctrl[4];        // [0]=base_bits [1]=hi_bits [2]=nsub
__device__ unsigned int       g_doneA;          // last-block counters (self-reset)
__device__ unsigned int       g_doneB;

__device__ __forceinline__ float bce_loss(float x, float t) {
    float e  = exp2f(fabsf(x) * -1.44269504f);
    float lg = __log2f(1.0f + e);
    float r  = __fmaf_rn(-x, t, fmaxf(x, 0.0f));
    return __fmaf_rn(0.69314718f, lg, r);   // >= 0 (r,lg >= 0)
}

// ============ Kernel A: sampled histogram + (last block) select ============
__global__ void __launch_bounds__(512) k_sample_select(const float4* __restrict__ p,
                                                       const float4* __restrict__ t,
                                                       int nchunks,
                                                       unsigned long long ks) {
    __shared__ unsigned sh[HISTW_N];          // 2 x u16 counters per word
    for (int j = threadIdx.x; j < HISTW_N; j += 512) sh[j] = 0u;
    __syncthreads();

    int stride = gridDim.x * blockDim.x;
    for (int s = blockIdx.x * blockDim.x + threadIdx.x; s < nchunks; s += stride) {
        float4 xp = p[s];
        float4 xt = t[s];
        unsigned b;
        b = __float_as_uint(bce_loss(xp.x, xt.x)) >> HIST_SHIFT;
        atomicAdd(&sh[b >> 1], (b & 1u) ? 65536u : 1u);
        b = __float_as_uint(bce_loss(xp.y, xt.y)) >> HIST_SHIFT;
        atomicAdd(&sh[b >> 1], (b & 1u) ? 65536u : 1u);
        b = __float_as_uint(bce_loss(xp.z, xt.z)) >> HIST_SHIFT;
        atomicAdd(&sh[b >> 1], (b & 1u) ? 65536u : 1u);
        b = __float_as_uint(bce_loss(xp.w, xt.w)) >> HIST_SHIFT;
        atomicAdd(&sh[b >> 1], (b & 1u) ? 65536u : 1u);
    }
    __syncthreads();
    for (int j = threadIdx.x; j < HISTW_N; j += 512) {
        unsigned c = sh[j];
        if (c & 0xFFFFu) atomicAdd(&g_hist[2 * j],     c & 0xFFFFu);
        if (c >> 16)     atomicAdd(&g_hist[2 * j + 1], c >> 16);
    }

    // ---- last-block-done handoff ----
    __shared__ int isLast;
    __threadfence();
    if (threadIdx.x == 0) {
        unsigned prev = atomicAdd(&g_doneA, 1u);
        isLast = (prev == gridDim.x - 1);
    }
    __syncthreads();
    if (!isLast) return;
    __threadfence();

    // ---- select via shfl suffix scans (512 threads, 32 bins each) ----
    int tid  = threadIdx.x;
    int lane = tid & 31, wid = tid >> 5;

    unsigned v[32];
    unsigned long long own = 0;
    int cbase = tid * 32;
    #pragma unroll
    for (int j = 0; j < 32; j++) { v[j] = g_hist[cbase + j]; own += v[j]; }
    #pragma unroll
    for (int j = 0; j < 32; j++) g_hist[cbase + j] = 0u;   // self-clean

    unsigned long long s = own;
    #pragma unroll
    for (int off = 1; off < 32; off <<= 1) {
        unsigned long long u = __shfl_down_sync(0xffffffffu, s, off);
        if (lane + off < 32) s += u;
    }
    __shared__ unsigned long long wtot[16], wtail[17];
    if (lane == 0) wtot[wid] = s;
    __syncthreads();
    if (wid == 0) {
        unsigned long long ws = (lane < 16) ? wtot[lane] : 0ull;
        #pragma unroll
        for (int off = 1; off < 16; off <<= 1) {
            unsigned long long u = __shfl_down_sync(0xffffffffu, ws, off);
            if (lane + off < 16) ws += u;
        }
        if (lane < 16) wtail[lane] = ws;
        if (lane == 0) wtail[16] = 0ull;
    }
    __syncthreads();

    unsigned long long S = s + wtail[wid + 1];
    if (S >= ks && S - own < ks) {
        unsigned long long cum = S - own;
        int bstar = cbase;
        #pragma unroll
        for (int j = 31; j >= 0; j--) {
            cum += v[j];
            if (cum >= ks) { bstar = cbase + j; break; }
        }
        int blo = (bstar >= MARGIN) ? bstar - MARGIN : 0;
        int bhi = (bstar + MARGIN <= HIST_N - 1) ? bstar + MARGIN : HIST_N - 1;
        g_ctrl[0] = (unsigned)blo << HIST_SHIFT;
        g_ctrl[1] = (unsigned)(bhi + 1) << HIST_SHIFT;
        g_ctrl[2] = (((unsigned)(bhi - blo + 1)) << HIST_SHIFT) >> SUB_SHIFT;
    }
    if (tid == 0) g_doneA = 0;   // self-reset
}

// ============ Kernel B: pipelined main pass, branchless classify ===========
__device__ __forceinline__ void acc_elem(float x, float t,
                                         float Thi, float Tbase, unsigned base,
                                         unsigned* shsub,
                                         float& fsum, unsigned& lcnt) {
    float v = bce_loss(x, t);
    bool top = (v >= Thi);
    fsum += top ? v : 0.0f;
    lcnt += (unsigned)top;
    unsigned idx = (__float_as_uint(v) - base) >> SUB_SHIFT;
    if (!top && v >= Tbase) atomicAdd(&shsub[idx], 1u);   // @p ATOMS
}

__global__ void __launch_bounds__(512) k_main_final(const float4* __restrict__ p,
                                                    const float4* __restrict__ t,
                                                    int n4, long long n,
                                                    long long k,
                                                    float* __restrict__ out) {
    __shared__ unsigned shsub[SUB_N];
    for (int j = threadIdx.x; j < SUB_N; j += 512) shsub[j] = 0u;
    __syncthreads();

    const unsigned base  = g_ctrl[0];
    const unsigned hi    = g_ctrl[1];
    const float    Thi   = __uint_as_float(hi);
    const float    Tbase = __uint_as_float(base);
    float    fsum = 0.0f;
    unsigned lcnt = 0u;

    const unsigned stride = gridDim.x * blockDim.x;
    unsigned i = blockIdx.x * blockDim.x + threadIdx.x;
    const unsigned n4u = (unsigned)n4;

    if (i < n4u) {
        float4 a = p[i];
        float4 b = t[i];
        for (;;) {
            unsigned j = i + stride;
            if (j < n4u) {
                float4 an = p[j];                 // prefetch next iteration
                float4 bn = t[j];
                acc_elem(a.x, b.x, Thi, Tbase, base, shsub, fsum, lcnt);
                acc_elem(a.y, b.y, Thi, Tbase, base, shsub, fsum, lcnt);
                acc_elem(a.z, b.z, Thi, Tbase, base, shsub, fsum, lcnt);
                acc_elem(a.w, b.w, Thi, Tbase, base, shsub, fsum, lcnt);
                a = an; b = bn; i = j;
            } else {
                acc_elem(a.x, b.x, Thi, Tbase, base, shsub, fsum, lcnt);
                acc_elem(a.y, b.y, Thi, Tbase, base, shsub, fsum, lcnt);
                acc_elem(a.z, b.z, Thi, Tbase, base, shsub, fsum, lcnt);
                acc_elem(a.w, b.w, Thi, Tbase, base, shsub, fsum, lcnt);
                break;
            }
        }
    }
    if (blockIdx.x == 0 && threadIdx.x == 0) {   // scalar tail (n % 4)
        const float* ps = (const float*)p;
        const float* ts = (const float*)t;
        for (long long j = (long long)n4 * 4; j < n; j++)
            acc_elem(ps[j], ts[j], Thi, Tbase, base, shsub, fsum, lcnt);
    }

    // block reduce of sum/cnt
    for (int o = 16; o; o >>= 1) {
        fsum += __shfl_down_sync(0xffffffffu, fsum, o);
        lcnt += __shfl_down_sync(0xffffffffu, lcnt, o);
    }
    __shared__ float    ws[16];
    __shared__ unsigned wc[16];
    int wid = threadIdx.x >> 5, lane = threadIdx.x & 31;
    if (lane == 0) { ws[wid] = fsum; wc[wid] = lcnt; }
    __syncthreads();
    if (wid == 0) {
        float    v = (lane < 16) ? ws[lane] : 0.0f;
        unsigned c = (lane < 16) ? wc[lane] : 0u;
        for (int o = 8; o; o >>= 1) {
            v += __shfl_down_sync(0xffffffffu, v, o);
            c += __shfl_down_sync(0xffffffffu, c, o);
        }
        if (lane == 0) {
            atomicAdd(&g_sum, (double)v);
            atomicAdd(&g_cnt, (unsigned long long)c);
        }
    }

    // flush block-private sub-histogram (nonzero bins only)
    __syncthreads();
    for (int j = threadIdx.x; j < SUB_N; j += 512) {
        unsigned c = shsub[j];
        if (c) atomicAdd(&g_sub[j], c);
    }

    // ---- last-block-done handoff ----
    __shared__ int isLast;
    __threadfence();
    if (threadIdx.x == 0) {
        unsigned prev = atomicAdd(&g_doneB, 1u);
        isLast = (prev == gridDim.x - 1);
    }
    __syncthreads();
    if (!isLast) return;
    __threadfence();

    // ---- finalize (512 threads) ----
    __shared__ unsigned long long sufc[512];
    __shared__ double             sufw[512];
    int tid = threadIdx.x;
    int nsub = (int)g_ctrl[2];                 // <= 1280
    int per  = (nsub + 511) / 512;             // <= 3

    unsigned cs_loc[4];
    unsigned long long c = 0ull;
    double             w = 0.0;
    for (int j = 0; j < per; j++) {
        int s = tid * per + j;
        unsigned cs = (s < nsub) ? g_sub[s] : 0u;
        if (s < nsub) g_sub[s] = 0u;           // self-clean
        cs_loc[j] = cs;
        c += cs;
        if (cs)
            w += (double)cs *
                 (double)__uint_as_float(base + ((unsigned)s << SUB_SHIFT) +
                                         (1u << (SUB_SHIFT - 1)));
    }
    sufc[tid] = c; sufw[tid] = w;
    __syncthreads();
    for (int off = 1; off < 512; off <<= 1) {
        unsigned long long ac = (tid + off < 512) ? sufc[tid + off] : 0ull;
        double             aw = (tid + off < 512) ? sufw[tid + off] : 0.0;
        __syncthreads();
        sufc[tid] += ac; sufw[tid] += aw;
        __syncthreads();
    }

    double    sum_gt = g_sum;
    long long cnt    = (long long)g_cnt;
    __syncthreads();
    if (tid == 0) { g_sum = 0.0; g_cnt = 0ull; g_doneB = 0; }   // self-clean
    long long r = k - cnt;

    if (r <= 0) {
        if (tid == 0) {
            double edge = (double)__uint_as_float(hi);
            out[0] = (float)((sum_gt + (double)r * edge) / (double)k);
        }
        return;
    }
    if ((unsigned long long)r > sufc[0]) {
        if (tid == 0) {
            double res = (sum_gt + sufw[0] +
                          (double)(r - (long long)sufc[0]) *
                          (double)__uint_as_float(base)) / (double)k;
            out[0] = (float)res;
        }
        return;
    }

    unsigned long long nxtc = (tid < 511) ? sufc[tid + 1] : 0ull;
    double             nxtw = (tid < 511) ? sufw[tid + 1] : 0.0;
    if (sufc[tid] >= (unsigned long long)r && nxtc < (unsigned long long)r) {
        unsigned long long cum = nxtc;
        double             acc = nxtw;
        for (int j = per - 1; j >= 0; j--) {
            int s = tid * per + j;
            if (s >= nsub) continue;
            unsigned cs = cs_loc[j];
            double mid = (double)__uint_as_float(base + ((unsigned)s << SUB_SHIFT) +
                                                 (1u << (SUB_SHIFT - 1)));
            if (cum + cs >= (unsigned long long)r) {
                acc += (double)((unsigned long long)r - cum) * mid;
                out[0] = (float)((sum_gt + acc) / (double)k);
                break;
            } else {
                acc += (double)cs * mid;
                cum += cs;
            }
        }
    }
}

// ---------------- host ----------------
extern "C" void kernel_launch(void* const* d_in, const int* in_sizes, int n_in,
                              void* d_out, int out_size) {
    const float* pred = (const float*)d_in[0];
    const float* targ = (const float*)d_in[1];
    long long n  = (long long)in_sizes[0];
    int       n4 = (int)(n / 4);

    int nchunks = n4 / SAMPLE_DIV;
    if (nchunks < 1) nchunks = (n4 > 0) ? n4 : 1;
    unsigned long long sc = (unsigned long long)nchunks * 4ull;
    unsigned long long ks = (unsigned long long)(0.25 * (double)sc);
    if (ks < 1) ks = 1;
    long long kk = (long long)(0.25 * (double)n);
    if (kk < 1) kk = 1;

    k_sample_select<<<148, 512>>>((const float4*)pred, (const float4*)targ,
                                  nchunks, ks);
    k_main_final  <<<1184, 512>>>((const float4*)pred, (const float4*)targ,
                                  n4, n, kk, (float*)d_out);
}